// round 3
// baseline (speedup 1.0000x reference)
#include <cuda_runtime.h>
#include <cstdint>

// LSM_IniReconNet: per 32x32 patch p (flattened k = kh*32+kw):
//   meas[s] = sum_k p[k] * Ws[s,k]        (Ws: [256,1024] row-major)
//   y[k]    = sum_s meas[s] * Wi[k,s]     (Wi: [1024,256] row-major)
// 16 batches * 1024 patches = 16384 patches. Fused two-stage GEMM per CTA,
// T=64 patches/CTA, tf32 mma.sync with fp32 accumulation.

#define T_PATCH 64
#define N_CTA 256   // 16384 / 64
#define N_THREADS 256

// SMEM layout (floats):
//   Ms  [64][257]  meas (tf32-rounded), persistent across stages
//   Ps  [64][33]   stage-1 A chunk (patch rows)     } aliased by
//   Bs  [32][257]  stage-1 B chunk (Ws^T slice)     } Bs2 [64][129] in stage 2
#define MS_OFF   0
#define PS_OFF   (64 * 257)
#define BS_OFF   (PS_OFF + 64 * 33)
#define BS2_OFF  PS_OFF
#define SMEM_FLOATS (64 * 257 + 64 * 33 + 32 * 257)
#define SMEM_BYTES  (SMEM_FLOATS * 4)

__device__ __forceinline__ uint32_t f2tf(float f) {
    uint32_t u;
    asm("cvt.rna.tf32.f32 %0, %1;" : "=r"(u) : "f"(f));
    return u;
}

__device__ __forceinline__ void mma_tf32(float c[4], const uint32_t a[4],
                                         uint32_t b0, uint32_t b1) {
    asm volatile(
        "mma.sync.aligned.m16n8k8.row.col.f32.tf32.tf32.f32 "
        "{%0,%1,%2,%3}, {%4,%5,%6,%7}, {%8,%9}, {%0,%1,%2,%3};"
        : "+f"(c[0]), "+f"(c[1]), "+f"(c[2]), "+f"(c[3])
        : "r"(a[0]), "r"(a[1]), "r"(a[2]), "r"(a[3]), "r"(b0), "r"(b1));
}

__global__ void __launch_bounds__(N_THREADS, 1)
lsm_fused_kernel(const float* __restrict__ x, const float* __restrict__ ws,
                 const float* __restrict__ wi, float* __restrict__ y)
{
    extern __shared__ float smem[];
    float* Ms  = smem + MS_OFF;
    float* Ps  = smem + PS_OFF;
    float* Bs  = smem + BS_OFF;
    float* Bs2 = smem + BS2_OFF;

    const int tid  = threadIdx.x;
    const int warp = tid >> 5;
    const int lane = tid & 31;
    const int g  = lane >> 2;   // groupID (row within fragment)
    const int tc = lane & 3;    // thread-in-group
    const int p0 = blockIdx.x * T_PATCH;

    // ---------------- Stage 1: meas[64,256] = P[64,1024] @ Ws^T ----------------
    // warp tiling: (32m x 64n); wm in {0,1}, wn in {0..3}
    const int wm = warp & 1;
    const int wn = warp >> 1;

    float acc[2][8][4];
    #pragma unroll
    for (int i = 0; i < 2; i++)
        #pragma unroll
        for (int j = 0; j < 8; j++)
            #pragma unroll
            for (int k = 0; k < 4; k++) acc[i][j][k] = 0.f;

    for (int kc = 0; kc < 32; ++kc) {  // K chunk = one patch row (32 elems)
        // P chunk: Ps[p][kw] = x[b, bh*32+kc, bw*32+kw]  (coalesced over kw)
        #pragma unroll
        for (int i = 0; i < 8; ++i) {
            int e = tid + i * N_THREADS;       // 0..2047
            int p = e >> 5, kw = e & 31;
            int gp  = p0 + p;
            int b   = gp >> 10;
            int rem = gp & 1023;
            int bh = rem >> 5, bw = rem & 31;
            float v = x[((size_t)b << 20) +
                        (size_t)((bh << 5) + kc) * 1024 + (bw << 5) + kw];
            Ps[p * 33 + kw] = __uint_as_float(f2tf(v));
        }
        // Ws chunk transposed: Bs[kk][s] = Ws[s, kc*32+kk]  (coalesced over kk)
        #pragma unroll
        for (int i = 0; i < 32; ++i) {
            int e = tid + i * N_THREADS;       // 0..8191
            int kk = e & 31, s = e >> 5;
            Bs[kk * 257 + s] = __uint_as_float(f2tf(ws[s * 1024 + (kc << 5) + kk]));
        }
        __syncthreads();

        #pragma unroll
        for (int ks = 0; ks < 4; ++ks) {       // 4 x k8 steps
            uint32_t a[2][4];
            #pragma unroll
            for (int mf = 0; mf < 2; ++mf) {
                int r0 = wm * 32 + mf * 16 + g;
                int c0 = ks * 8 + tc;
                a[mf][0] = __float_as_uint(Ps[r0 * 33 + c0]);
                a[mf][1] = __float_as_uint(Ps[(r0 + 8) * 33 + c0]);
                a[mf][2] = __float_as_uint(Ps[r0 * 33 + c0 + 4]);
                a[mf][3] = __float_as_uint(Ps[(r0 + 8) * 33 + c0 + 4]);
            }
            #pragma unroll
            for (int nf = 0; nf < 8; ++nf) {
                int col = wn * 64 + nf * 8 + g;
                int kr  = ks * 8 + tc;
                uint32_t b0 = __float_as_uint(Bs[kr * 257 + col]);
                uint32_t b1 = __float_as_uint(Bs[(kr + 4) * 257 + col]);
                mma_tf32(acc[0][nf], a[0], b0, b1);
                mma_tf32(acc[1][nf], a[1], b0, b1);
            }
        }
        __syncthreads();
    }

    // Dump meas to SMEM (tf32-rounded once, so stage 2 reads operands directly)
    #pragma unroll
    for (int mf = 0; mf < 2; ++mf) {
        int r = wm * 32 + mf * 16 + g;
        #pragma unroll
        for (int nf = 0; nf < 8; ++nf) {
            int c = wn * 64 + nf * 8 + 2 * tc;
            Ms[r * 257 + c]           = __uint_as_float(f2tf(acc[mf][nf][0]));
            Ms[r * 257 + c + 1]       = __uint_as_float(f2tf(acc[mf][nf][1]));
            Ms[(r + 8) * 257 + c]     = __uint_as_float(f2tf(acc[mf][nf][2]));
            Ms[(r + 8) * 257 + c + 1] = __uint_as_float(f2tf(acc[mf][nf][3]));
        }
    }
    __syncthreads();

    // ---------------- Stage 2: Y[64,1024] = meas[64,256] @ Wi^T ----------------
    // per 128-col output chunk; warp tiling (32m x 32n): wm as before, wn 0..3
    for (int nc = 0; nc < 8; ++nc) {
        float acc2[2][4][4];
        #pragma unroll
        for (int i = 0; i < 2; i++)
            #pragma unroll
            for (int j = 0; j < 4; j++)
                #pragma unroll
                for (int k = 0; k < 4; k++) acc2[i][j][k] = 0.f;

        for (int sc = 0; sc < 4; ++sc) {   // K chunk of 64 over s
            // Bs2[ss][n] = Wi[nc*128+n, sc*64+ss]  (coalesced over ss)
            #pragma unroll
            for (int i = 0; i < 32; ++i) {
                int e = tid + i * N_THREADS;   // 0..8191
                int ss = e & 63, n = e >> 6;
                Bs2[ss * 129 + n] =
                    __uint_as_float(f2tf(wi[(nc * 128 + n) * 256 + (sc << 6) + ss]));
            }
            __syncthreads();

            #pragma unroll
            for (int ks = 0; ks < 8; ++ks) {
                uint32_t a[2][4];
                #pragma unroll
                for (int mf = 0; mf < 2; ++mf) {
                    int r0 = wm * 32 + mf * 16 + g;
                    int c0 = sc * 64 + ks * 8 + tc;
                    a[mf][0] = __float_as_uint(Ms[r0 * 257 + c0]);
                    a[mf][1] = __float_as_uint(Ms[(r0 + 8) * 257 + c0]);
                    a[mf][2] = __float_as_uint(Ms[r0 * 257 + c0 + 4]);
                    a[mf][3] = __float_as_uint(Ms[(r0 + 8) * 257 + c0 + 4]);
                }
                #pragma unroll
                for (int nf = 0; nf < 4; ++nf) {
                    int col = wn * 32 + nf * 8 + g;
                    int kr  = ks * 8 + tc;
                    uint32_t b0 = __float_as_uint(Bs2[kr * 129 + col]);
                    uint32_t b1 = __float_as_uint(Bs2[(kr + 4) * 129 + col]);
                    mma_tf32(acc2[0][nf], a[0], b0, b1);
                    mma_tf32(acc2[1][nf], a[1], b0, b1);
                }
            }
            __syncthreads();
        }

        // Epilogue: fold back to image layout, float2 (8B) stores
        #pragma unroll
        for (int mf = 0; mf < 2; ++mf) {
            #pragma unroll
            for (int half = 0; half < 2; ++half) {
                int r   = wm * 32 + mf * 16 + g + half * 8;
                int gp  = p0 + r;
                int b   = gp >> 10;
                int rem = gp & 1023;
                int bh = rem >> 5, bw = rem & 31;
                #pragma unroll
                for (int nf = 0; nf < 4; ++nf) {
                    int c  = nc * 128 + wn * 32 + nf * 8 + 2 * tc;
                    int kh = c >> 5, kw = c & 31;   // kw even -> 8B aligned
                    float2 v;
                    v.x = acc2[mf][nf][half * 2 + 0];
                    v.y = acc2[mf][nf][half * 2 + 1];
                    *reinterpret_cast<float2*>(
                        &y[((size_t)b << 20) +
                           (size_t)((bh << 5) + kh) * 1024 + (bw << 5) + kw]) = v;
                }
            }
        }
    }
}

extern "C" void kernel_launch(void* const* d_in, const int* in_sizes, int n_in,
                              void* d_out, int out_size)
{
    const float* x  = (const float*)d_in[0];   // [16,1,1024,1024]
    const float* ws = (const float*)d_in[1];   // [256,1024]
    const float* wi = (const float*)d_in[2];   // [1024,256]
    float* y = (float*)d_out;                  // [16,1,1024,1024]

    cudaFuncSetAttribute(lsm_fused_kernel,
                         cudaFuncAttributeMaxDynamicSharedMemorySize, SMEM_BYTES);
    lsm_fused_kernel<<<N_CTA, N_THREADS, SMEM_BYTES>>>(x, ws, wi, y);
}

// round 4
// speedup vs baseline: 1.1796x; 1.1796x over previous
#include <cuda_runtime.h>
#include <cstdint>

// LSM_IniReconNet fused two-stage GEMM, tf32 mma.sync, fragment-pair SMEM
// layouts so every MMA operand load is a single LDS.128 / LDS.64, and all
// shared reads/writes are bank-conflict-free.
//
//   stage 1: meas[64,256] = P[64,1024] @ Ws^T
//   stage 2: Y[64,1024]   = meas @ Wi^T
// 256 CTAs x 256 threads, 64 patches/CTA.

#define N_THREADS 256
#define N_CTA 256

// SMEM strides (floats)
#define MH_STRIDE 528   // Ms: 32 g-rows (x quad-packed 256 k)  ; 528 % 32 == 16
#define A1_STRIDE 80    // stage-1 A: 32 g-rows                 ; 80  % 32 == 16
#define B1_STRIDE 520   // stage-1 B: 16 (ks*4+tc) slices       ; 520 % 32 == 8
#define B2_STRIDE 520   // stage-2 B: 32 slices

#define MH_OFF 0
#define A1_OFF (32 * MH_STRIDE)             // 16896
#define B1_OFF (A1_OFF + 32 * A1_STRIDE)    // 19456
#define B2_OFF A1_OFF                       // aliases A1+B1 (stage 2 only)
#define SMEM_FLOATS (A1_OFF + 32 * B2_STRIDE)   // 33536
#define SMEM_BYTES (SMEM_FLOATS * 4)            // 134144

__device__ __forceinline__ uint32_t f2tf(float f) {
    uint32_t u;
    asm("cvt.rna.tf32.f32 %0, %1;" : "=r"(u) : "f"(f));
    return u;
}
__device__ __forceinline__ float tfv(float f) { return __uint_as_float(f2tf(f)); }

__device__ __forceinline__ void mma_tf32(float c[4], const uint32_t a[4],
                                         uint32_t b0, uint32_t b1) {
    asm volatile(
        "mma.sync.aligned.m16n8k8.row.col.f32.tf32.tf32.f32 "
        "{%0,%1,%2,%3}, {%4,%5,%6,%7}, {%8,%9}, {%0,%1,%2,%3};"
        : "+f"(c[0]), "+f"(c[1]), "+f"(c[2]), "+f"(c[3])
        : "r"(a[0]), "r"(a[1]), "r"(a[2]), "r"(a[3]), "r"(b0), "r"(b1));
}

__global__ void __launch_bounds__(N_THREADS, 1)
lsm_fused_kernel(const float* __restrict__ x, const float* __restrict__ ws,
                 const float* __restrict__ wi, float* __restrict__ y)
{
    extern __shared__ float sm[];
    float* MH = sm + MH_OFF;
    float* A1 = sm + A1_OFF;
    float* B1 = sm + B1_OFF;
    float* B2 = sm + B2_OFF;

    const int tid  = threadIdx.x;
    const int warp = tid >> 5;
    const int lane = tid & 31;
    const int g  = lane >> 2;      // fragment groupID (row)
    const int tc = lane & 3;       // thread-in-group
    const int wm = warp & 1;       // m-tile of warp (32 rows)
    const int wn = warp >> 1;      // n-tile of warp (64 cols)
    const int p0 = blockIdx.x * 64;

    // ---------------- per-thread loader precompute ----------------
    // Stage-1 A (x patches): 2 float4 / thread / kc.  v = tid + i*256:
    //   p = v>>3 (patch), kq = v&7 (float4 within 32-wide patch row)
    size_t a_goff[2]; int a_soff[2];
    #pragma unroll
    for (int i = 0; i < 2; ++i) {
        int v = tid + i * 256;
        int p = v >> 3, kq = v & 7;
        int gp = p0 + p;
        int b = gp >> 10, rem = gp & 1023, bh = rem >> 5, bw = rem & 31;
        a_goff[i] = ((size_t)b << 20) + (size_t)(bh << 5) * 1024 + (bw << 5) + (kq << 2);
        // A1[row(p)] packed: quad q = (k>>3)*4 + (k&3); comp = (p>>3 &1) + 2*(k>>2 &1)
        a_soff[i] = ((p >> 4) * 8 + (p & 7)) * A1_STRIDE
                    + (kq >> 1) * 16 + ((p >> 3) & 1) + 2 * (kq & 1);
    }
    // Stage-1 B (Ws): 8 float4 / thread / kc.
    //   s = i*32 + (tid>>7)*16 + (tid&15), kq = (tid>>4)&7  (conflict-free STS)
    const int s_b  = ((tid >> 7) & 1) * 16 + (tid & 15);
    const int kq_b = (tid >> 4) & 7;
    const int b1_soff = ((kq_b >> 1) * 4) * B1_STRIDE + s_b * 2 + (kq_b & 1);
    // Stage-2 B (Wi): 16 float4 / thread / (nc,sc).
    //   n = i*16 + (tid&15), sq = tid>>4  (conflict-free STS, coalesced LDG)
    const int n_lo = tid & 15;
    const int sq   = tid >> 4;
    const int b2_soff = ((sq >> 1) * 4) * B2_STRIDE + n_lo * 2 + (sq & 1);

    // ================= Stage 1: meas = P @ Ws^T =================
    float acc[2][8][4];
    #pragma unroll
    for (int i = 0; i < 2; i++)
        #pragma unroll
        for (int j = 0; j < 8; j++)
            #pragma unroll
            for (int k = 0; k < 4; k++) acc[i][j][k] = 0.f;

    for (int kc = 0; kc < 32; ++kc) {
        // --- A chunk: 64 patches x 32 k (row kc of each patch) ---
        #pragma unroll
        for (int i = 0; i < 2; ++i) {
            const float4 f = *reinterpret_cast<const float4*>(
                x + a_goff[i] + (size_t)kc * 1024);
            float* a = A1 + a_soff[i];
            a[0]  = tfv(f.x);
            a[4]  = tfv(f.y);
            a[8]  = tfv(f.z);
            a[12] = tfv(f.w);
        }
        // --- B chunk: Ws[:, kc*32 .. +31] transposed-pair-packed ---
        #pragma unroll
        for (int i = 0; i < 8; ++i) {
            int s = i * 32 + s_b;
            const float4 f = *reinterpret_cast<const float4*>(
                ws + (size_t)s * 1024 + (kc << 5) + (kq_b << 2));
            float* bsl = B1 + b1_soff + i * 64;      // s*2 advances by 64
            bsl[0 * B1_STRIDE] = tfv(f.x);
            bsl[1 * B1_STRIDE] = tfv(f.y);
            bsl[2 * B1_STRIDE] = tfv(f.z);
            bsl[3 * B1_STRIDE] = tfv(f.w);
        }
        __syncthreads();

        #pragma unroll
        for (int ks = 0; ks < 4; ++ks) {
            uint32_t a[2][4];
            #pragma unroll
            for (int mf = 0; mf < 2; ++mf) {
                int gi = wm * 2 + mf;
                const float4 fa = *reinterpret_cast<const float4*>(
                    &A1[(gi * 8 + g) * A1_STRIDE + (ks * 4 + tc) * 4]);
                a[mf][0] = __float_as_uint(fa.x);
                a[mf][1] = __float_as_uint(fa.y);
                a[mf][2] = __float_as_uint(fa.z);
                a[mf][3] = __float_as_uint(fa.w);
            }
            #pragma unroll
            for (int nf = 0; nf < 8; ++nf) {
                int col = wn * 64 + nf * 8 + g;
                const float2 fb = *reinterpret_cast<const float2*>(
                    &B1[(ks * 4 + tc) * B1_STRIDE + col * 2]);
                uint32_t b0 = __float_as_uint(fb.x);
                uint32_t b1 = __float_as_uint(fb.y);
                mma_tf32(acc[0][nf], a[0], b0, b1);
                mma_tf32(acc[1][nf], a[1], b0, b1);
            }
        }
        __syncthreads();
    }

    // --- dump meas to MH (tf32-rounded once), quad-packed like A1 ---
    #pragma unroll
    for (int mf = 0; mf < 2; ++mf) {
        int rowb = ((wm * 2 + mf) * 8 + g) * MH_STRIDE;
        #pragma unroll
        for (int nf = 0; nf < 8; ++nf) {
            // c = wn*64 + nf*8 + 2*tc ; quad = (c>>3)*4 + (c&3) ; comp = r8 + 2*(c>>2&1)
            int qb = rowb + (wn * 8 + nf) * 16 + 2 * (tc >> 1);
            int t0 = qb + (2 * (tc & 1)) * 4;       // col c
            int t1 = qb + (2 * (tc & 1) + 1) * 4;   // col c+1
            MH[t0]     = tfv(acc[mf][nf][0]);   // (r0,   c)
            MH[t1]     = tfv(acc[mf][nf][1]);   // (r0,   c+1)
            MH[t0 + 1] = tfv(acc[mf][nf][2]);   // (r0+8, c)
            MH[t1 + 1] = tfv(acc[mf][nf][3]);   // (r0+8, c+1)
        }
    }
    __syncthreads();

    // ================= Stage 2: Y = meas @ Wi^T =================
    for (int nc = 0; nc < 4; ++nc) {            // 256 output cols per chunk
        float acc2[2][8][4];
        #pragma unroll
        for (int i = 0; i < 2; i++)
            #pragma unroll
            for (int j = 0; j < 8; j++)
                #pragma unroll
                for (int k = 0; k < 4; k++) acc2[i][j][k] = 0.f;

        for (int sc = 0; sc < 4; ++sc) {        // 64-wide k chunk over s
            // --- B2 chunk: Wi[nc*256 .. +255, sc*64 .. +63] pair-packed ---
            #pragma unroll
            for (int i = 0; i < 16; ++i) {
                int n = i * 16 + n_lo;
                const float4 f = *reinterpret_cast<const float4*>(
                    wi + (size_t)(nc * 256 + n) * 256 + (sc << 6) + (sq << 2));
                float* bsl = B2 + b2_soff + i * 32;   // n*2 advances by 32
                bsl[0 * B2_STRIDE] = tfv(f.x);
                bsl[1 * B2_STRIDE] = tfv(f.y);
                bsl[2 * B2_STRIDE] = tfv(f.z);
                bsl[3 * B2_STRIDE] = tfv(f.w);
            }
            __syncthreads();

            #pragma unroll
            for (int ks = 0; ks < 8; ++ks) {
                uint32_t a[2][4];
                #pragma unroll
                for (int mf = 0; mf < 2; ++mf) {
                    int gi = wm * 2 + mf;
                    const float4 fa = *reinterpret_cast<const float4*>(
                        &MH[(gi * 8 + g) * MH_STRIDE + ((sc * 8 + ks) * 4 + tc) * 4]);
                    a[mf][0] = __float_as_uint(fa.x);
                    a[mf][1] = __float_as_uint(fa.y);
                    a[mf][2] = __float_as_uint(fa.z);
                    a[mf][3] = __float_as_uint(fa.w);
                }
                #pragma unroll
                for (int nf = 0; nf < 8; ++nf) {
                    int col = wn * 64 + nf * 8 + g;
                    const float2 fb = *reinterpret_cast<const float2*>(
                        &B2[(ks * 4 + tc) * B2_STRIDE + col * 2]);
                    uint32_t b0 = __float_as_uint(fb.x);
                    uint32_t b1 = __float_as_uint(fb.y);
                    mma_tf32(acc2[0][nf], a[0], b0, b1);
                    mma_tf32(acc2[1][nf], a[1], b0, b1);
                }
            }
            __syncthreads();
        }

        // --- epilogue: fold back to image, 8B stores, fully coalesced ---
        #pragma unroll
        for (int mf = 0; mf < 2; ++mf) {
            #pragma unroll
            for (int half = 0; half < 2; ++half) {
                int r   = wm * 32 + mf * 16 + g + half * 8;
                int gp  = p0 + r;
                int b   = gp >> 10;
                int rem = gp & 1023;
                int bh = rem >> 5, bw = rem & 31;
                float* yb = y + ((size_t)b << 20) + (size_t)(bh << 5) * 1024 + (bw << 5);
                #pragma unroll
                for (int nf = 0; nf < 8; ++nf) {
                    int c  = nc * 256 + wn * 64 + nf * 8 + 2 * tc;
                    int kh = c >> 5, kw = c & 31;
                    float2 v2;
                    v2.x = acc2[mf][nf][half * 2 + 0];
                    v2.y = acc2[mf][nf][half * 2 + 1];
                    *reinterpret_cast<float2*>(yb + (size_t)kh * 1024 + kw) = v2;
                }
            }
        }
    }
}

extern "C" void kernel_launch(void* const* d_in, const int* in_sizes, int n_in,
                              void* d_out, int out_size)
{
    const float* x  = (const float*)d_in[0];   // [16,1,1024,1024]
    const float* ws = (const float*)d_in[1];   // [256,1024]
    const float* wi = (const float*)d_in[2];   // [1024,256]
    float* y = (float*)d_out;                  // [16,1,1024,1024]

    cudaFuncSetAttribute(lsm_fused_kernel,
                         cudaFuncAttributeMaxDynamicSharedMemorySize, SMEM_BYTES);
    lsm_fused_kernel<<<N_CTA, N_THREADS, SMEM_BYTES>>>(x, ws, wi, y);
}

// round 6
// speedup vs baseline: 1.6510x; 1.3997x over previous
#include <cuda_runtime.h>
#include <cstdint>

// LSM_IniReconNet fused two-stage GEMM, tf32 mma.sync.
//   stage 1: meas[64,256] = P[64,1024] @ Ws^T   (Ws [256,1024] row-major)
//   stage 2: Y[64,1024]   = meas @ Wi^T         (Wi [1024,256] row-major)
// Both weight matrices are already in mma.row.col B (col-major-over-k) order,
// so B fragments load DIRECTLY from global (LDG + cvt.rna.tf32) — no B smem,
// no stage-2 barriers. A patches double-buffered in smem (1 sync / k-chunk).
// 256 CTAs x 256 threads, 2 CTAs/SM (88KB smem, <=128 regs) -> single wave.

#define N_THREADS 256
#define N_CTA 256

#define MH_STRIDE 528            // 528 % 32 == 16 (conflict-free LDS.128)
#define A_STRIDE  80             // 80  % 32 == 16
#define A_BUF     (32 * A_STRIDE)        // 2560 floats per buffer
#define MH_OFF    0
#define A_OFF     (32 * MH_STRIDE)       // 16896
#define SMEM_FLOATS (A_OFF + 2 * A_BUF)  // 22016
#define SMEM_BYTES  (SMEM_FLOATS * 4)    // 88064

__device__ __forceinline__ uint32_t f2tf(float f) {
    uint32_t u;
    asm("cvt.rna.tf32.f32 %0, %1;" : "=r"(u) : "f"(f));
    return u;
}
__device__ __forceinline__ float tfv(float f) { return __uint_as_float(f2tf(f)); }

__device__ __forceinline__ void mma_tf32(float c[4], const uint32_t a[4],
                                         uint32_t b0, uint32_t b1) {
    asm volatile(
        "mma.sync.aligned.m16n8k8.row.col.f32.tf32.tf32.f32 "
        "{%0,%1,%2,%3}, {%4,%5,%6,%7}, {%8,%9}, {%0,%1,%2,%3};"
        : "+f"(c[0]), "+f"(c[1]), "+f"(c[2]), "+f"(c[3])
        : "r"(a[0]), "r"(a[1]), "r"(a[2]), "r"(a[3]), "r"(b0), "r"(b1));
}

__global__ void __launch_bounds__(N_THREADS, 2)
lsm_fused_kernel(const float* __restrict__ x, const float* __restrict__ ws,
                 const float* __restrict__ wi, float* __restrict__ y)
{
    extern __shared__ float sm[];
    float* MH = sm + MH_OFF;
    float* AB = sm + A_OFF;          // two A buffers of A_BUF floats

    const int tid  = threadIdx.x;
    const int warp = tid >> 5;       // 0..7 : owns n-cols [warp*32, +32)
    const int lane = tid & 31;
    const int g  = lane >> 2;
    const int tc = lane & 3;
    const int p0 = blockIdx.x * 64;

    // ---- A loader precompute: 2 float4 / thread / kc ----
    size_t a_goff[2]; int a_soff[2];
    #pragma unroll
    for (int i = 0; i < 2; ++i) {
        int v = tid + i * 256;
        int p = v >> 3, kq = v & 7;
        int gp = p0 + p;
        int b = gp >> 10, rem = gp & 1023, bh = rem >> 5, bw = rem & 31;
        a_goff[i] = ((size_t)b << 20) + (size_t)(bh << 5) * 1024 + (bw << 5) + (kq << 2);
        a_soff[i] = ((p >> 4) * 8 + (p & 7)) * A_STRIDE
                    + (kq >> 1) * 16 + ((p >> 3) & 1) + 2 * (kq & 1);
    }

    // stage-1 B base: Ws[col][k], col = warp*32 + nf*8 + g, k = kc*32+ks*8+tc
    const float* wsp = ws + (size_t)(warp * 32 + g) * 1024 + tc;

    // ---- prologue: stage A(kc=0) ----
    #pragma unroll
    for (int i = 0; i < 2; ++i) {
        const float4 f = *reinterpret_cast<const float4*>(x + a_goff[i]);
        float* a = AB + a_soff[i];
        a[0] = tfv(f.x); a[4] = tfv(f.y); a[8] = tfv(f.z); a[12] = tfv(f.w);
    }
    __syncthreads();

    // ================= Stage 1 =================
    float acc[4][4][4];
    #pragma unroll
    for (int i = 0; i < 4; i++)
        #pragma unroll
        for (int j = 0; j < 4; j++)
            #pragma unroll
            for (int k = 0; k < 4; k++) acc[i][j][k] = 0.f;

    for (int kc = 0; kc < 32; ++kc) {
        // prefetch next A chunk (global -> regs) while computing
        float4 pf[2];
        const bool pre = (kc < 31);
        if (pre) {
            #pragma unroll
            for (int i = 0; i < 2; ++i)
                pf[i] = *reinterpret_cast<const float4*>(
                    x + a_goff[i] + (size_t)(kc + 1) * 1024);
        }

        const float* Ab = AB + (kc & 1) * A_BUF;
        const float* wk = wsp + (kc << 5);

        #pragma unroll
        for (int ks = 0; ks < 4; ++ks) {
            uint32_t bb[4][2];
            #pragma unroll
            for (int nf = 0; nf < 4; ++nf) {
                bb[nf][0] = f2tf(wk[nf * 8192 + ks * 8]);
                bb[nf][1] = f2tf(wk[nf * 8192 + ks * 8 + 4]);
            }
            #pragma unroll
            for (int mf = 0; mf < 4; ++mf) {
                const float4 fa = *reinterpret_cast<const float4*>(
                    &Ab[(mf * 8 + g) * A_STRIDE + (ks * 4 + tc) * 4]);
                uint32_t a4[4] = {__float_as_uint(fa.x), __float_as_uint(fa.y),
                                  __float_as_uint(fa.z), __float_as_uint(fa.w)};
                #pragma unroll
                for (int nf = 0; nf < 4; ++nf)
                    mma_tf32(acc[mf][nf], a4, bb[nf][0], bb[nf][1]);
            }
        }

        if (pre) {
            float* Aw = AB + ((kc + 1) & 1) * A_BUF;
            #pragma unroll
            for (int i = 0; i < 2; ++i) {
                float* a = Aw + a_soff[i];
                a[0] = tfv(pf[i].x); a[4]  = tfv(pf[i].y);
                a[8] = tfv(pf[i].z); a[12] = tfv(pf[i].w);
            }
        }
        __syncthreads();
    }

    // ---- dump meas to MH (quad-packed, tf32-rounded once) ----
    #pragma unroll
    for (int mf = 0; mf < 4; ++mf) {
        int rowb = (mf * 8 + g) * MH_STRIDE;
        #pragma unroll
        for (int nf = 0; nf < 4; ++nf) {
            int qb = rowb + (warp * 4 + nf) * 16 + 2 * (tc >> 1) + 8 * (tc & 1);
            MH[qb]     = tfv(acc[mf][nf][0]);   // (r,   c)
            MH[qb + 4] = tfv(acc[mf][nf][1]);   // (r,   c+1)
            MH[qb + 1] = tfv(acc[mf][nf][2]);   // (r+8, c)
            MH[qb + 5] = tfv(acc[mf][nf][3]);   // (r+8, c+1)
        }
    }
    __syncthreads();

    // ================= Stage 2 (no barriers) =================
    // B base: Wi[kout][s], kout = nc*256 + warp*32 + nf*8 + g, s = ks*8+tc
    const float* wip = wi + (size_t)(warp * 32 + g) * 256 + tc;

    for (int nc = 0; nc < 4; ++nc) {
        float acc2[4][4][4];
        #pragma unroll
        for (int i = 0; i < 4; i++)
            #pragma unroll
            for (int j = 0; j < 4; j++)
                #pragma unroll
                for (int k = 0; k < 4; k++) acc2[i][j][k] = 0.f;

        const float* wn_ = wip + (size_t)nc * 65536;

        #pragma unroll 4
        for (int ks = 0; ks < 32; ++ks) {
            uint32_t bb[4][2];
            #pragma unroll
            for (int nf = 0; nf < 4; ++nf) {
                bb[nf][0] = f2tf(wn_[nf * 2048 + ks * 8]);
                bb[nf][1] = f2tf(wn_[nf * 2048 + ks * 8 + 4]);
            }
            #pragma unroll
            for (int mf = 0; mf < 4; ++mf) {
                const float4 fa = *reinterpret_cast<const float4*>(
                    &MH[(mf * 8 + g) * MH_STRIDE + (ks * 4 + tc) * 4]);
                uint32_t a4[4] = {__float_as_uint(fa.x), __float_as_uint(fa.y),
                                  __float_as_uint(fa.z), __float_as_uint(fa.w)};
                #pragma unroll
                for (int nf = 0; nf < 4; ++nf)
                    mma_tf32(acc2[mf][nf], a4, bb[nf][0], bb[nf][1]);
            }
        }

        // epilogue: c = nc*256 + warp*32 + nf*8 + 2tc -> kh = nc*8+warp, kw = nf*8+2tc
        const int kh = nc * 8 + warp;
        #pragma unroll
        for (int mf = 0; mf < 4; ++mf) {
            #pragma unroll
            for (int half = 0; half < 2; ++half) {
                int r   = mf * 16 + g + 8 * half;
                int gp  = p0 + r;
                int b   = gp >> 10;
                int rem = gp & 1023;
                int bh = rem >> 5, bw = rem & 31;
                float* yb = y + ((size_t)b << 20)
                              + (size_t)((bh << 5) + kh) * 1024 + (bw << 5);
                #pragma unroll
                for (int nf = 0; nf < 4; ++nf) {
                    float2 v2;
                    v2.x = acc2[mf][nf][half * 2 + 0];
                    v2.y = acc2[mf][nf][half * 2 + 1];
                    *reinterpret_cast<float2*>(yb + nf * 8 + 2 * tc) = v2;
                }
            }
        }
    }
}

extern "C" void kernel_launch(void* const* d_in, const int* in_sizes, int n_in,
                              void* d_out, int out_size)
{
    const float* x  = (const float*)d_in[0];   // [16,1,1024,1024]
    const float* ws = (const float*)d_in[1];   // [256,1024]
    const float* wi = (const float*)d_in[2];   // [1024,256]
    float* y = (float*)d_out;                  // [16,1,1024,1024]

    cudaFuncSetAttribute(lsm_fused_kernel,
                         cudaFuncAttributeMaxDynamicSharedMemorySize, SMEM_BYTES);
    lsm_fused_kernel<<<N_CTA, N_THREADS, SMEM_BYTES>>>(x, ws, wi, y);
}

// round 7
// speedup vs baseline: 3.0053x; 1.8202x over previous
#include <cuda_runtime.h>
#include <cstdint>

// LSM_IniReconNet fused two-stage GEMM, tf32 mma.sync.
//   stage 1: meas[64,256] = P[64,1024] @ Ws^T   (Ws [256,1024] row-major)
//   stage 2: Y[64,1024]   = meas @ Wi^T         (Wi [1024,256] row-major)
// K-slot permutation (k = 16*ks2 + 4*tc + 2*s + d) makes every B fragment a
// single coalesced LDG.128 serving two MMA steps; A tiles in smem absorb the
// permutation in the loader scatter, keeping conflict-free LDS.128 fragments.
// No B smem, no stage-2 barriers. 256 CTAs x 256 thr, 2 CTAs/SM, one wave.

#define N_THREADS 256
#define N_CTA 256

#define MH_STRIDE 528            // % 32 == 16 -> conflict-free LDS.128
#define A_STRIDE  80             // % 32 == 16
#define A_BUF     (32 * A_STRIDE)
#define MH_OFF    0
#define A_OFF     (32 * MH_STRIDE)
#define SMEM_FLOATS (A_OFF + 2 * A_BUF)
#define SMEM_BYTES  (SMEM_FLOATS * 4)    // 88064

__device__ __forceinline__ uint32_t f2tf(float f) {
    uint32_t u;
    asm("cvt.rna.tf32.f32 %0, %1;" : "=r"(u) : "f"(f));
    return u;
}
__device__ __forceinline__ float tfv(float f) { return __uint_as_float(f2tf(f)); }

__device__ __forceinline__ void mma_tf32(float c[4], const uint32_t a[4],
                                         uint32_t b0, uint32_t b1) {
    asm volatile(
        "mma.sync.aligned.m16n8k8.row.col.f32.tf32.tf32.f32 "
        "{%0,%1,%2,%3}, {%4,%5,%6,%7}, {%8,%9}, {%0,%1,%2,%3};"
        : "+f"(c[0]), "+f"(c[1]), "+f"(c[2]), "+f"(c[3])
        : "r"(a[0]), "r"(a[1]), "r"(a[2]), "r"(a[3]), "r"(b0), "r"(b1));
}

__global__ void __launch_bounds__(N_THREADS, 2)
lsm_fused_kernel(const float* __restrict__ x, const float* __restrict__ ws,
                 const float* __restrict__ wi, float* __restrict__ y)
{
    extern __shared__ float sm[];
    float* MH = sm + MH_OFF;
    float* AB = sm + A_OFF;

    const int tid  = threadIdx.x;
    const int warp = tid >> 5;       // owns n-cols [warp*32, +32)
    const int lane = tid & 31;
    const int g  = lane >> 2;
    const int tc = lane & 3;
    const int p0 = blockIdx.x * 64;

    // ---- A loader precompute (permuted scatter): 2 float4 / thread / kc ----
    size_t a_goff[2]; int a_soff[2];
    #pragma unroll
    for (int i = 0; i < 2; ++i) {
        int v = tid + i * 256;
        int p = v >> 3, kq = v & 7;
        int gp = p0 + p;
        int b = gp >> 10, rem = gp & 1023, bh = rem >> 5, bw = rem & 31;
        a_goff[i] = ((size_t)b << 20) + (size_t)(bh << 5) * 1024 + (bw << 5) + (kq << 2);
        a_soff[i] = ((p >> 4) * 8 + (p & 7)) * A_STRIDE
                    + 32 * (kq >> 2) + 4 * (kq & 3) + ((p >> 3) & 1);
    }

    // weight base pointers: row = warp*32 + nf*8 + g, inner offset 4*tc
    const float* wsp = ws + (size_t)(warp * 32 + g) * 1024 + (tc << 2);
    const float* wip = wi + (size_t)(warp * 32 + g) * 256 + (tc << 2);

    // ---- prologue: stage A(kc=0) ----
    #pragma unroll
    for (int i = 0; i < 2; ++i) {
        const float4 f = *reinterpret_cast<const float4*>(x + a_goff[i]);
        float* a = AB + a_soff[i];
        a[0] = tfv(f.x); a[2] = tfv(f.y); a[16] = tfv(f.z); a[18] = tfv(f.w);
    }
    __syncthreads();

    // ================= Stage 1 =================
    float acc[4][4][4];
    #pragma unroll
    for (int i = 0; i < 4; i++)
        #pragma unroll
        for (int j = 0; j < 4; j++)
            #pragma unroll
            for (int k = 0; k < 4; k++) acc[i][j][k] = 0.f;

    for (int kc = 0; kc < 32; ++kc) {
        float4 pf[2];
        const bool pre = (kc < 31);
        if (pre) {
            #pragma unroll
            for (int i = 0; i < 2; ++i)
                pf[i] = *reinterpret_cast<const float4*>(
                    x + a_goff[i] + (size_t)(kc + 1) * 1024);
        }

        const float* Ab = AB + (kc & 1) * A_BUF;
        const float* wk = wsp + (kc << 5);

        #pragma unroll
        for (int ks2 = 0; ks2 < 2; ++ks2) {
            // one LDG.128 per nf serves two MMA steps (coalesced 8x64B)
            float4 Bf[4];
            #pragma unroll
            for (int nf = 0; nf < 4; ++nf)
                Bf[nf] = *reinterpret_cast<const float4*>(wk + nf * 8192 + ks2 * 16);
            uint32_t bb[4][4];
            #pragma unroll
            for (int nf = 0; nf < 4; ++nf) {
                bb[nf][0] = f2tf(Bf[nf].x); bb[nf][1] = f2tf(Bf[nf].y);
                bb[nf][2] = f2tf(Bf[nf].z); bb[nf][3] = f2tf(Bf[nf].w);
            }
            #pragma unroll
            for (int s = 0; s < 2; ++s) {
                const int ks = ks2 * 2 + s;
                #pragma unroll
                for (int mf = 0; mf < 4; ++mf) {
                    const float4 fa = *reinterpret_cast<const float4*>(
                        &Ab[(mf * 8 + g) * A_STRIDE + (ks * 4 + tc) * 4]);
                    uint32_t a4[4] = {__float_as_uint(fa.x), __float_as_uint(fa.y),
                                      __float_as_uint(fa.z), __float_as_uint(fa.w)};
                    #pragma unroll
                    for (int nf = 0; nf < 4; ++nf)
                        mma_tf32(acc[mf][nf], a4, bb[nf][2 * s], bb[nf][2 * s + 1]);
                }
            }
        }

        if (pre) {
            float* Aw = AB + ((kc + 1) & 1) * A_BUF;
            #pragma unroll
            for (int i = 0; i < 2; ++i) {
                float* a = Aw + a_soff[i];
                a[0]  = tfv(pf[i].x); a[2]  = tfv(pf[i].y);
                a[16] = tfv(pf[i].z); a[18] = tfv(pf[i].w);
            }
        }
        __syncthreads();
    }

    // ---- dump meas to MH at permuted slot positions (STS.128 each) ----
    #pragma unroll
    for (int mf = 0; mf < 4; ++mf) {
        #pragma unroll
        for (int nf = 0; nf < 4; ++nf) {
            int off = (mf * 8 + g) * MH_STRIDE + 64 * warp + 32 * (nf >> 1)
                    + 16 * (tc & 1) + 4 * ((2 * nf + (tc >> 1)) & 3);
            float4 v;
            v.x = tfv(acc[mf][nf][0]);   // (r,   c)   comp 0
            v.y = tfv(acc[mf][nf][2]);   // (r+8, c)   comp 1
            v.z = tfv(acc[mf][nf][1]);   // (r,   c+1) comp 2
            v.w = tfv(acc[mf][nf][3]);   // (r+8, c+1) comp 3
            *reinterpret_cast<float4*>(MH + off) = v;
        }
    }
    __syncthreads();

    // ================= Stage 2 (no barriers) =================
    for (int nc = 0; nc < 4; ++nc) {
        float acc2[4][4][4];
        #pragma unroll
        for (int i = 0; i < 4; i++)
            #pragma unroll
            for (int j = 0; j < 4; j++)
                #pragma unroll
                for (int k = 0; k < 4; k++) acc2[i][j][k] = 0.f;

        const float* wn_ = wip + (size_t)nc * 65536;

        #pragma unroll 2
        for (int ks2 = 0; ks2 < 16; ++ks2) {
            float4 Bf[4];
            #pragma unroll
            for (int nf = 0; nf < 4; ++nf)
                Bf[nf] = *reinterpret_cast<const float4*>(wn_ + nf * 2048 + ks2 * 16);
            uint32_t bb[4][4];
            #pragma unroll
            for (int nf = 0; nf < 4; ++nf) {
                bb[nf][0] = f2tf(Bf[nf].x); bb[nf][1] = f2tf(Bf[nf].y);
                bb[nf][2] = f2tf(Bf[nf].z); bb[nf][3] = f2tf(Bf[nf].w);
            }
            #pragma unroll
            for (int s = 0; s < 2; ++s) {
                const int ks = ks2 * 2 + s;
                #pragma unroll
                for (int mf = 0; mf < 4; ++mf) {
                    const float4 fa = *reinterpret_cast<const float4*>(
                        &MH[(mf * 8 + g) * MH_STRIDE + (ks * 4 + tc) * 4]);
                    uint32_t a4[4] = {__float_as_uint(fa.x), __float_as_uint(fa.y),
                                      __float_as_uint(fa.z), __float_as_uint(fa.w)};
                    #pragma unroll
                    for (int nf = 0; nf < 4; ++nf)
                        mma_tf32(acc2[mf][nf], a4, bb[nf][2 * s], bb[nf][2 * s + 1]);
                }
            }
        }

        // epilogue: c = nc*256 + warp*32 + nf*8 + 2tc -> kh = nc*8+warp
        const int kh = nc * 8 + warp;
        #pragma unroll
        for (int mf = 0; mf < 4; ++mf) {
            #pragma unroll
            for (int half = 0; half < 2; ++half) {
                int r   = mf * 16 + g + 8 * half;
                int gp  = p0 + r;
                int b   = gp >> 10;
                int rem = gp & 1023;
                int bh = rem >> 5, bw = rem & 31;
                float* yb = y + ((size_t)b << 20)
                              + (size_t)((bh << 5) + kh) * 1024 + (bw << 5);
                #pragma unroll
                for (int nf = 0; nf < 4; ++nf) {
                    float2 v2;
                    v2.x = acc2[mf][nf][half * 2 + 0];
                    v2.y = acc2[mf][nf][half * 2 + 1];
                    *reinterpret_cast<float2*>(yb + nf * 8 + 2 * tc) = v2;
                }
            }
        }
    }
}

extern "C" void kernel_launch(void* const* d_in, const int* in_sizes, int n_in,
                              void* d_out, int out_size)
{
    const float* x  = (const float*)d_in[0];   // [16,1,1024,1024]
    const float* ws = (const float*)d_in[1];   // [256,1024]
    const float* wi = (const float*)d_in[2];   // [1024,256]
    float* y = (float*)d_out;                  // [16,1,1024,1024]

    cudaFuncSetAttribute(lsm_fused_kernel,
                         cudaFuncAttributeMaxDynamicSharedMemorySize, SMEM_BYTES);
    lsm_fused_kernel<<<N_CTA, N_THREADS, SMEM_BYTES>>>(x, ws, wi, y);
}